// round 16
// baseline (speedup 1.0000x reference)
#include <cuda_runtime.h>
#include <cuda_bf16.h>
#include <cstdint>

// Problem constants
#define N_ROWS 32768
#define C_DIM  256
#define K_DIM  1024

// Output layout
#define OFF_QUANT 0
#define OFF_EMB   8388608
#define OFF_CS    8650752
#define OFF_DW    8651776
#define OFF_LOSS  8913920
#define OFF_PERP  8913921

// Tile image geometry: tile = 128 rows x 32 bf16 cols, rows padded to 80B.
#define TILE_B   10240          // 128*80
#define SLAB_B   (8 * TILE_B)   // full K=256 for one 128-row block

#define RSLOTS 8                // slots per (row, CTA) region
#define MARGIN 2.5e-3f

// ------------------------- device scratch -------------------------
__device__ float  g_embT[K_DIM * C_DIM];
__device__ float  g_colnorm[K_DIM];
__device__ float  g_rownorm[N_ROWS];
__device__ __align__(128) unsigned char g_Aimg[256 * SLAB_B]; // 21 MB
__device__ __align__(128) unsigned char g_Bimg[8 * SLAB_B];
__device__ int    g_ccnt8[N_ROWS * 8];                        // per (row, CTA) count
__device__ __align__(16) float2 g_cand[N_ROWS * 64];          // {approx d, bits(col)}
__device__ int    g_idx[N_ROWS];
__device__ int    g_counts[K_DIM];
__device__ int    g_base[K_DIM];
__device__ int    g_rows[N_ROWS];
__device__ float  g_smoothed[K_DIM];
__device__ double g_loss;

// ------------------------- PTX helpers -------------------------
__device__ __forceinline__ uint32_t smem_u32(const void* p) {
    uint32_t a;
    asm("{ .reg .u64 t; cvta.to.shared.u64 t, %1; cvt.u32.u64 %0, t; }" : "=r"(a) : "l"(p));
    return a;
}
#define MBAR_INIT(a, c) asm volatile("mbarrier.init.shared.b64 [%0], %1;" :: "r"(a), "r"(c) : "memory")
#define MBAR_EXPECT(a, n) asm volatile("mbarrier.arrive.expect_tx.shared.b64 _, [%0], %1;" :: "r"(a), "r"(n) : "memory")
#define MBAR_ARRIVE(a) asm volatile("mbarrier.arrive.shared.b64 _, [%0];" :: "r"(a) : "memory")

__device__ __forceinline__ void mbar_wait(uint32_t mbar, uint32_t parity) {
    asm volatile(
        "{\n\t.reg .pred P1;\n\t"
        "WAIT_LOOP_%=:\n\t"
        "mbarrier.try_wait.parity.shared.b64 P1, [%0], %1;\n\t"
        "@P1 bra.uni WAIT_DONE_%=;\n\t"
        "bra.uni WAIT_LOOP_%=;\n\t"
        "WAIT_DONE_%=:\n\t}"
        :: "r"(mbar), "r"(parity) : "memory");
}
__device__ __forceinline__ void bulk_g2s(uint32_t dst, const void* src, uint32_t bytes,
                                         uint32_t mbar) {
    asm volatile(
        "cp.async.bulk.shared::cta.global.mbarrier::complete_tx::bytes [%0], [%1], %2, [%3];"
        :: "r"(dst), "l"(src), "r"(bytes), "r"(mbar) : "memory");
}
__device__ __forceinline__ void ldsm4(uint32_t* r, uint32_t addr) {
    asm volatile("ldmatrix.sync.aligned.m8n8.x4.shared.b16 {%0,%1,%2,%3}, [%4];"
        : "=r"(r[0]), "=r"(r[1]), "=r"(r[2]), "=r"(r[3]) : "r"(addr));
}
__device__ __forceinline__ void mma16816(float (&d)[4], const uint32_t (&a)[4],
                                         uint32_t b0, uint32_t b1) {
    asm volatile("mma.sync.aligned.m16n8k16.row.col.f32.bf16.bf16.f32 "
        "{%0,%1,%2,%3}, {%4,%5,%6,%7}, {%8,%9}, {%0,%1,%2,%3};"
        : "+f"(d[0]), "+f"(d[1]), "+f"(d[2]), "+f"(d[3])
        : "r"(a[0]), "r"(a[1]), "r"(a[2]), "r"(a[3]), "r"(b0), "r"(b1));
}

__device__ __forceinline__ void st_bf16x4(unsigned char* dst, float f0, float f1,
                                          float f2, float f3) {
    __align__(8) __nv_bfloat16 c[4];
    c[0] = __float2bfloat16(f0); c[1] = __float2bfloat16(f1);
    c[2] = __float2bfloat16(f2); c[3] = __float2bfloat16(f3);
    *(uint2*)dst = *(const uint2*)c;
}

// ------------------------- K1: colnorm + B image + embT + init (fused) --------
__global__ void k_colnormB(const float* __restrict__ emb) {
    if (blockIdx.x == 0) {                     // fused init (disjoint data)
        int t = threadIdx.x;
#pragma unroll
        for (int j = 0; j < 4; j++) g_counts[t + j * 256] = 0;
        if (t == 0) g_loss = 0.0;
    }
    int w = threadIdx.x >> 5, l = threadIdx.x & 31;
    int k = blockIdx.x * 8 + w;
    float a[4], b[4];
#pragma unroll
    for (int j = 0; j < 4; j++) a[j] = emb[(size_t)(4 * l + j) * 1024 + k];
#pragma unroll
    for (int j = 0; j < 4; j++) b[j] = emb[(size_t)(128 + 4 * l + j) * 1024 + k];
    float s = a[0] * a[0] + a[1] * a[1] + a[2] * a[2] + a[3] * a[3]
            + b[0] * b[0] + b[1] * b[1] + b[2] * b[2] + b[3] * b[3];
#pragma unroll
    for (int o = 16; o; o >>= 1) s += __shfl_xor_sync(0xFFFFFFFFu, s, o);
    if (l == 0) g_colnorm[k] = s;
    float4* et = (float4*)(g_embT + (size_t)k * 256);
    et[l]      = make_float4(a[0], a[1], a[2], a[3]);
    et[l + 32] = make_float4(b[0], b[1], b[2], b[3]);
    size_t base = (size_t)(k >> 7) * SLAB_B + (size_t)(k & 127) * 80 + (l & 7) * 8;
    st_bf16x4(g_Bimg + base + (size_t)(l >> 3) * TILE_B, a[0], a[1], a[2], a[3]);
    st_bf16x4(g_Bimg + base + (size_t)(4 + (l >> 3)) * TILE_B, b[0], b[1], b[2], b[3]);
}

// ------------------------- K2: rownorm + A image -------------------------------
__global__ void k_prepA(const float* __restrict__ x) {
    int w = threadIdx.x >> 5, l = threadIdx.x & 31;
    int n = blockIdx.x * 8 + w;
    const float4* p = (const float4*)(x + (size_t)n * C_DIM);
    float4 a = p[l];
    float4 b = p[l + 32];
    float s = a.x * a.x + a.y * a.y + a.z * a.z + a.w * a.w
            + b.x * b.x + b.y * b.y + b.z * b.z + b.w * b.w;
#pragma unroll
    for (int o = 16; o; o >>= 1) s += __shfl_xor_sync(0xFFFFFFFFu, s, o);
    if (l == 0) g_rownorm[n] = s;
    size_t base = (size_t)(n >> 7) * SLAB_B + (size_t)(n & 127) * 80 + (l & 7) * 8;
    st_bf16x4(g_Aimg + base + (size_t)(l >> 3) * TILE_B, a.x, a.y, a.z, a.w);
    st_bf16x4(g_Aimg + base + (size_t)(4 + (l >> 3)) * TILE_B, b.x, b.y, b.z, b.w);
}

// ------------------------- K3: bf16 GEMM (round-15 config, unchanged) ----------
#define NSTAGE 4
#define ST_BO  10240
#define STAGE  20480
#define SMEM_GEMM 83968          // 2048 header + 4*20480
// header: cnt_s[128] @0 | rowmin[128][2] @512 | full[4] @1536 | empty[4] @1568

__global__ void __launch_bounds__(256, 2) k_gemm_mma() {
    extern __shared__ char smem[];
    uint32_t sb = smem_u32(smem);
    int tid = threadIdx.x, w = tid >> 5, l = tid & 31;
    int wm = w & 3, wn = w >> 2;
    int bx = blockIdx.x, by = blockIdx.y;

    int*   cnt_s  = (int*)smem;                 // [128]
    float* rowmin = (float*)(smem + 512);       // [128][2]
    if (tid < 128) cnt_s[tid] = 0;
    if (tid < NSTAGE) {
        MBAR_INIT(sb + 1536 + 8 * tid, 1);      // full
        MBAR_INIT(sb + 1568 + 8 * tid, 8);      // empty (8 warps)
    }
    __syncthreads();

    const unsigned char* Ag = g_Aimg + (size_t)by * SLAB_B;
    const unsigned char* Bg = g_Bimg + (size_t)bx * SLAB_B;
    uint32_t st_base = sb + 2048;

    if (tid == 0) {
#pragma unroll
        for (int p = 0; p < NSTAGE; p++) {
            MBAR_EXPECT(sb + 1536 + 8 * p, STAGE);
            bulk_g2s(st_base + p * STAGE,         Ag + p * TILE_B, TILE_B, sb + 1536 + 8 * p);
            bulk_g2s(st_base + p * STAGE + ST_BO, Bg + p * TILE_B, TILE_B, sb + 1536 + 8 * p);
        }
    }

    float acc[2][8][4];
#pragma unroll
    for (int f = 0; f < 2; f++)
#pragma unroll
        for (int t = 0; t < 8; t++)
#pragma unroll
            for (int j = 0; j < 4; j++) acc[f][t][j] = 0.f;

    uint32_t lrow = l & 15, lk = (l >> 4) * 16;
    uint32_t a0_off = (wm * 32 + lrow) * 80 + lk;
    uint32_t a1_off = a0_off + 16 * 80;
    uint32_t b_off  = ST_BO + (wn * 64 + lrow) * 80 + lk;

    for (int ks = 0; ks < 8; ks++) {
        int slot = ks & 3;
        mbar_wait(sb + 1536 + 8 * slot, (uint32_t)((ks >> 2) & 1));

        uint32_t base = st_base + slot * STAGE;
#pragma unroll
        for (int s = 0; s < 2; s++) {
            uint32_t A0[4], A1[4];
            ldsm4(A0, base + a0_off + s * 32);
            ldsm4(A1, base + a1_off + s * 32);
#pragma unroll
            for (int p = 0; p < 4; p++) {
                uint32_t B[4];
                ldsm4(B, base + b_off + p * 1280 + s * 32);
                mma16816(acc[0][2 * p],     A0, B[0], B[2]);
                mma16816(acc[0][2 * p + 1], A0, B[1], B[3]);
                mma16816(acc[1][2 * p],     A1, B[0], B[2]);
                mma16816(acc[1][2 * p + 1], A1, B[1], B[3]);
            }
        }
        if (l == 0) MBAR_ARRIVE(sb + 1568 + 8 * slot);

        if (w == 0 && ks < 4) {
            mbar_wait(sb + 1568 + 8 * slot, 0u);
            if (l == 0) {
                MBAR_EXPECT(sb + 1536 + 8 * slot, STAGE);
                bulk_g2s(st_base + slot * STAGE,         Ag + (ks + 4) * TILE_B, TILE_B, sb + 1536 + 8 * slot);
                bulk_g2s(st_base + slot * STAGE + ST_BO, Bg + (ks + 4) * TILE_B, TILE_B, sb + 1536 + 8 * slot);
            }
        }
    }

    // ---- Epilogue phase 1: per-(row, warp) mins -> rowmin[lr][wn] ----
    float rn[2][2];
#pragma unroll
    for (int f = 0; f < 2; f++) {
        int lr0 = wm * 32 + f * 16 + (l >> 2);
        rn[f][0] = g_rownorm[by * 128 + lr0];
        rn[f][1] = g_rownorm[by * 128 + lr0 + 8];
        float bv0 = 3.4e38f, bv1 = 3.4e38f;
#pragma unroll
        for (int t = 0; t < 8; t++) {
#pragma unroll
            for (int j = 0; j < 2; j++) {
                bv0 = fminf(bv0, rn[f][0] - 2.0f * acc[f][t][j]);
                bv1 = fminf(bv1, rn[f][1] - 2.0f * acc[f][t][j + 2]);
            }
        }
#pragma unroll
        for (int m = 1; m <= 2; m <<= 1) {
            bv0 = fminf(bv0, __shfl_xor_sync(0xFFFFFFFFu, bv0, m));
            bv1 = fminf(bv1, __shfl_xor_sync(0xFFFFFFFFu, bv1, m));
        }
        if ((l & 3) == 0) {
            int lr = wm * 32 + f * 16 + (l >> 2);
            rowmin[lr * 2 + wn]       = bv0;
            rowmin[(lr + 8) * 2 + wn] = bv1;
        }
    }
    __syncthreads();

    // ---- Epilogue phase 2: threshold = CTA-min(128 codes) + MARGIN; append ----
#pragma unroll
    for (int f = 0; f < 2; f++) {
        int lr0 = wm * 32 + f * 16 + (l >> 2);
        int r0 = by * 128 + lr0;
        float th0 = fminf(rowmin[lr0 * 2], rowmin[lr0 * 2 + 1]) + MARGIN;
        float th1 = fminf(rowmin[(lr0 + 8) * 2], rowmin[(lr0 + 8) * 2 + 1]) + MARGIN;
#pragma unroll
        for (int t = 0; t < 8; t++) {
#pragma unroll
            for (int j = 0; j < 2; j++) {
                int col = (bx * 2 + wn) * 64 + t * 8 + 2 * (l & 3) + j;
                float d0 = rn[f][0] - 2.0f * acc[f][t][j];
                float d1 = rn[f][1] - 2.0f * acc[f][t][j + 2];
                if (d0 <= th0) {
                    int pos = atomicAdd(&cnt_s[lr0], 1);
                    if (pos < RSLOTS)
                        g_cand[(size_t)r0 * 64 + bx * RSLOTS + pos] =
                            make_float2(d0, __int_as_float(col));
                }
                if (d1 <= th1) {
                    int pos = atomicAdd(&cnt_s[lr0 + 8], 1);
                    if (pos < RSLOTS)
                        g_cand[(size_t)(r0 + 8) * 64 + bx * RSLOTS + pos] =
                            make_float2(d1, __int_as_float(col));
                }
            }
        }
    }
    __syncthreads();
    if (tid < 128) {
        int c = cnt_s[tid];
        g_ccnt8[(by * 128 + tid) * 8 + bx] = c < RSLOTS ? c : RSLOTS;
    }
}

// ------------------------- K4: refine (round-15 version, unchanged) ------------
__global__ void __launch_bounds__(256) k_refineq(const float* __restrict__ x,
                                                 float* __restrict__ out_quant) {
    __shared__ float xs[2048];
    __shared__ float ws[8];
    __shared__ int   cbuf[8][32];
    int tid = threadIdx.x, w = tid >> 5, l = tid & 31;
    int row = blockIdx.x * 8 + w;

    const float2* cp = &g_cand[(size_t)row * 64];
    float2 c0 = cp[l];
    float2 c1 = cp[l + 32];
    int cntv = (l < 8) ? g_ccnt8[(size_t)row * 8 + l] : 0;
    const float4* xg = (const float4*)(x + (size_t)row * 256);
    float4 xa = xg[l];
    float4 xb = xg[l + 32];
    float rnv = g_rownorm[row];

    float4* xrow4 = (float4*)(xs + w * 256);
    xrow4[l]      = xa;
    xrow4[l + 32] = xb;

    int cnt_r0 = __shfl_sync(0xFFFFFFFFu, cntv, l >> 3);
    int cnt_r1 = __shfl_sync(0xFFFFFFFFu, cntv, 4 + (l >> 3));
    int s_in = l & 7;
    bool val0 = s_in < cnt_r0;
    bool val1 = s_in < cnt_r1;

    float m0 = val0 ? c0.x : 3.4e38f;
    float m1 = val1 ? c1.x : 3.4e38f;
    float cm = fminf(m0, m1);
#pragma unroll
    for (int o = 16; o; o >>= 1) cm = fminf(cm, __shfl_xor_sync(0xFFFFFFFFu, cm, o));
    float thresh = cm + MARGIN;

    int v0 = (val0 && c0.x <= thresh) ? 1 : 0;
    int v1 = (val1 && c1.x <= thresh) ? 1 : 0;
    int nv = v0 + v1;
    int pre = nv;
#pragma unroll
    for (int o = 1; o < 32; o <<= 1) {
        int t = __shfl_up_sync(0xFFFFFFFFu, pre, o);
        if (l >= o) pre += t;
    }
    int excl = pre - nv;
    int total = __shfl_sync(0xFFFFFFFFu, pre, 31);
    if (total > 32) total = 32;

    int* buf = cbuf[w];
    int p = excl;
    if (v0 && p < 32) buf[p++] = __float_as_int(c0.y);
    if (v1 && p < 32) buf[p++] = __float_as_int(c1.y);
    __syncwarp();

    int k;
    if (total == 1) {
        k = buf[0];
    } else {
        int mycand = (l < total) ? buf[l] : -1;
        float dval = 3.4e38f;
        int   didx = 0x7FFFFFFF;
        if (mycand >= 0) {
            const float4* e4 = (const float4*)(g_embT + (size_t)mycand * 256);
            const float4* x4 = (const float4*)(xs + w * 256);
            float acc = 0.f;
#pragma unroll 4
            for (int i = 0; i < 64; i++) {
                float4 e = e4[i];
                float4 xv = x4[i];
                acc = fmaf(xv.x, e.x, acc);
                acc = fmaf(xv.y, e.y, acc);
                acc = fmaf(xv.z, e.z, acc);
                acc = fmaf(xv.w, e.w, acc);
            }
            dval = (rnv - 2.0f * acc) + g_colnorm[mycand];
            didx = mycand;
        }
#pragma unroll
        for (int o = 16; o; o >>= 1) {
            float ov = __shfl_xor_sync(0xFFFFFFFFu, dval, o);
            int   oi = __shfl_xor_sync(0xFFFFFFFFu, didx, o);
            if (ov < dval || (ov == dval && oi < didx)) { dval = ov; didx = oi; }
        }
        k = didx;
    }
    if (l == 0) {
        g_idx[row] = k;
        atomicAdd(&g_counts[k], 1);
    }

    const float4* e4 = (const float4*)(g_embT + (size_t)k * 256);
    float4 ea = e4[l];
    float4 eb = e4[l + 32];
    float4* q4 = (float4*)(out_quant + (size_t)row * 256);
    float lsum = 0.f;
    {
        float dx = ea.x - xa.x, dy = ea.y - xa.y, dz = ea.z - xa.z, dw2 = ea.w - xa.w;
        float4 o;
        o.x = xa.x + dx; o.y = xa.y + dy; o.z = xa.z + dz; o.w = xa.w + dw2;
        q4[l] = o;
        lsum += dx * dx + dy * dy + dz * dz + dw2 * dw2;
    }
    {
        float dx = eb.x - xb.x, dy = eb.y - xb.y, dz = eb.z - xb.z, dw2 = eb.w - xb.w;
        float4 o;
        o.x = xb.x + dx; o.y = xb.y + dy; o.z = xb.z + dz; o.w = xb.w + dw2;
        q4[l + 32] = o;
        lsum += dx * dx + dy * dy + dz * dz + dw2 * dw2;
    }
#pragma unroll
    for (int o = 16; o; o >>= 1) lsum += __shfl_xor_sync(0xFFFFFFFFu, lsum, o);
    if (l == 0) ws[w] = lsum;
    __syncthreads();
    if (tid < 8) {
        float v = ws[tid];
#pragma unroll
        for (int o = 4; o; o >>= 1) v += __shfl_xor_sync(0x000000FFu, v, o);
        if (tid == 0) atomicAdd(&g_loss, (double)v);
    }
}

// ------------------------- K5: scan + fused row-bucketing ----------------------
// 1 block, 1024 threads: prefix sums, cs/n/smoothed/perp/loss, then buckets all
// 32768 rows into g_rows via a shared-memory cursor (replaces k_fill).
__global__ void k_scan(const float* __restrict__ ema_cs, float* __restrict__ out) {
    __shared__ int   si[1024];
    __shared__ float red[1024];
    __shared__ int   scur[1024];
    int t = threadIdx.x;
    int cnt = g_counts[t];

    si[t] = cnt; __syncthreads();
    for (int o = 1; o < 1024; o <<= 1) {
        int v = (t >= o) ? si[t - o] : 0;
        __syncthreads();
        si[t] += v;
        __syncthreads();
    }
    int mybase = si[t] - cnt;
    g_base[t] = mybase;
    scur[t] = mybase;

    float cs = ema_cs[t] * 0.99f + (float)cnt * 0.01f;
    out[OFF_CS + t] = cs;

    red[t] = cs; __syncthreads();
    for (int s = 512; s > 0; s >>= 1) {
        if (t < s) red[t] += red[t + s];
        __syncthreads();
    }
    float n = red[0];
    __syncthreads();

    float p = (float)cnt / 32768.0f;
    red[t] = p * logf(p + 1e-10f); __syncthreads();
    for (int s = 512; s > 0; s >>= 1) {
        if (t < s) red[t] += red[t + s];
        __syncthreads();
    }
    if (t == 0) {
        out[OFF_PERP] = expf(-red[0]);
        out[OFF_LOSS] = 0.25f * (float)(g_loss / 8388608.0);
    }
    g_smoothed[t] = (cs + 1e-5f) / (n + 0.01024f) * n;

    // fused bucketing: 32 rows per thread, smem cursor (absolute positions)
    __syncthreads();
#pragma unroll 4
    for (int r = t; r < N_ROWS; r += 1024) {
        int k = g_idx[r];
        int pos = atomicAdd(&scur[k], 1);
        g_rows[pos] = r;
    }
}

// ------------------------- K6: dw + new embeddings (fused) ---------------------
__global__ void k_dw(const float* __restrict__ x,
                     const float* __restrict__ ema_dw,
                     float* __restrict__ out) {
    int k = blockIdx.x, c = threadIdx.x;
    int cnt = g_counts[k], base = g_base[k];
    float a0 = 0.f, a1 = 0.f, a2 = 0.f, a3 = 0.f;
    int i = 0;
    for (; i + 4 <= cnt; i += 4) {
        int r0 = g_rows[base + i],     r1 = g_rows[base + i + 1];
        int r2 = g_rows[base + i + 2], r3 = g_rows[base + i + 3];
        a0 += x[(size_t)r0 * 256 + c];
        a1 += x[(size_t)r1 * 256 + c];
        a2 += x[(size_t)r2 * 256 + c];
        a3 += x[(size_t)r3 * 256 + c];
    }
    for (; i < cnt; i++) a0 += x[(size_t)g_rows[base + i] * 256 + c];
    float sum = (a0 + a1) + (a2 + a3);
    float dwv = ema_dw[c * 1024 + k] * 0.99f + 0.01f * sum;
    out[OFF_DW  + c * 1024 + k] = dwv;
    out[OFF_EMB + c * 1024 + k] = dwv / g_smoothed[k];
}

// ------------------------- launch -------------------------
extern "C" void kernel_launch(void* const* d_in, const int* in_sizes, int n_in,
                              void* d_out, int out_size) {
    const float* x      = (const float*)d_in[0];
    const float* emb    = (const float*)d_in[1];
    const float* ema_cs = (const float*)d_in[2];
    const float* ema_dw = (const float*)d_in[3];
    float* out = (float*)d_out;

    cudaFuncSetAttribute(k_gemm_mma, cudaFuncAttributeMaxDynamicSharedMemorySize,
                         SMEM_GEMM);

    k_colnormB  <<<128, 256>>>(emb);                              // 1
    k_prepA     <<<4096, 256>>>(x);                               // 2
    k_gemm_mma  <<<dim3(8, 256), 256, SMEM_GEMM>>>();             // 3
    k_refineq   <<<4096, 256>>>(x, out + OFF_QUANT);              // 4 (profiled)
    k_scan      <<<1, 1024>>>(ema_cs, out);                       // 5
    k_dw        <<<1024, 256>>>(x, ema_dw, out);                  // 6
}

// round 17
// speedup vs baseline: 1.1021x; 1.1021x over previous
#include <cuda_runtime.h>
#include <cuda_bf16.h>
#include <cstdint>

// Problem constants
#define N_ROWS 32768
#define C_DIM  256
#define K_DIM  1024

// Output layout
#define OFF_QUANT 0
#define OFF_EMB   8388608
#define OFF_CS    8650752
#define OFF_DW    8651776
#define OFF_LOSS  8913920
#define OFF_PERP  8913921

// Tile image geometry: tile = 128 rows x 32 bf16 cols, rows padded to 80B.
#define TILE_B   10240          // 128*80
#define SLAB_B   (8 * TILE_B)   // full K=256 for one 128-row block

#define RSLOTS 8                // slots per (row, CTA) region
#define MARGIN 2.5e-3f

// ------------------------- device scratch -------------------------
__device__ float  g_embT[K_DIM * C_DIM];
__device__ float  g_colnorm[K_DIM];
__device__ float  g_rownorm[N_ROWS];
__device__ __align__(128) unsigned char g_Aimg[256 * SLAB_B]; // 21 MB
__device__ __align__(128) unsigned char g_Bimg[8 * SLAB_B];
__device__ int    g_ccnt8[N_ROWS * 8];                        // per (row, CTA) count
__device__ __align__(16) float2 g_cand[N_ROWS * 64];          // {approx d, bits(col)}
__device__ int    g_idx[N_ROWS];
__device__ int    g_counts[K_DIM];
__device__ int    g_base[K_DIM];
__device__ int    g_cursor[K_DIM];
__device__ int    g_rows[N_ROWS];
__device__ float  g_smoothed[K_DIM];
__device__ double g_loss;

// ------------------------- PTX helpers -------------------------
__device__ __forceinline__ uint32_t smem_u32(const void* p) {
    uint32_t a;
    asm("{ .reg .u64 t; cvta.to.shared.u64 t, %1; cvt.u32.u64 %0, t; }" : "=r"(a) : "l"(p));
    return a;
}
#define MBAR_INIT(a, c) asm volatile("mbarrier.init.shared.b64 [%0], %1;" :: "r"(a), "r"(c) : "memory")
#define MBAR_EXPECT(a, n) asm volatile("mbarrier.arrive.expect_tx.shared.b64 _, [%0], %1;" :: "r"(a), "r"(n) : "memory")
#define MBAR_ARRIVE(a) asm volatile("mbarrier.arrive.shared.b64 _, [%0];" :: "r"(a) : "memory")

__device__ __forceinline__ void mbar_wait(uint32_t mbar, uint32_t parity) {
    asm volatile(
        "{\n\t.reg .pred P1;\n\t"
        "WAIT_LOOP_%=:\n\t"
        "mbarrier.try_wait.parity.shared.b64 P1, [%0], %1;\n\t"
        "@P1 bra.uni WAIT_DONE_%=;\n\t"
        "bra.uni WAIT_LOOP_%=;\n\t"
        "WAIT_DONE_%=:\n\t}"
        :: "r"(mbar), "r"(parity) : "memory");
}
__device__ __forceinline__ void bulk_g2s(uint32_t dst, const void* src, uint32_t bytes,
                                         uint32_t mbar) {
    asm volatile(
        "cp.async.bulk.shared::cta.global.mbarrier::complete_tx::bytes [%0], [%1], %2, [%3];"
        :: "r"(dst), "l"(src), "r"(bytes), "r"(mbar) : "memory");
}
__device__ __forceinline__ void ldsm4(uint32_t* r, uint32_t addr) {
    asm volatile("ldmatrix.sync.aligned.m8n8.x4.shared.b16 {%0,%1,%2,%3}, [%4];"
        : "=r"(r[0]), "=r"(r[1]), "=r"(r[2]), "=r"(r[3]) : "r"(addr));
}
__device__ __forceinline__ void mma16816(float (&d)[4], const uint32_t (&a)[4],
                                         uint32_t b0, uint32_t b1) {
    asm volatile("mma.sync.aligned.m16n8k16.row.col.f32.bf16.bf16.f32 "
        "{%0,%1,%2,%3}, {%4,%5,%6,%7}, {%8,%9}, {%0,%1,%2,%3};"
        : "+f"(d[0]), "+f"(d[1]), "+f"(d[2]), "+f"(d[3])
        : "r"(a[0]), "r"(a[1]), "r"(a[2]), "r"(a[3]), "r"(b0), "r"(b1));
}

__device__ __forceinline__ void st_bf16x4(unsigned char* dst, float f0, float f1,
                                          float f2, float f3) {
    __align__(8) __nv_bfloat16 c[4];
    c[0] = __float2bfloat16(f0); c[1] = __float2bfloat16(f1);
    c[2] = __float2bfloat16(f2); c[3] = __float2bfloat16(f3);
    *(uint2*)dst = *(const uint2*)c;
}

// ------------------------- K0: init -------------------------
__global__ void k_init() {
    int i = threadIdx.x;
    g_counts[i] = 0;
    g_cursor[i] = 0;
    if (i == 0) g_loss = 0.0;
}

// ------------------------- K1: merged prep -------------------------------------
// Blocks 0..127: colnorm + B image + embT (transpose). Blocks 128..4223: rownorm
// + A image. Identical arithmetic to the round-15 separate kernels.
__global__ void k_prep(const float* __restrict__ emb, const float* __restrict__ x) {
    int w = threadIdx.x >> 5, l = threadIdx.x & 31;
    if (blockIdx.x < 128) {
        int k = blockIdx.x * 8 + w;
        float a[4], b[4];
#pragma unroll
        for (int j = 0; j < 4; j++) a[j] = emb[(size_t)(4 * l + j) * 1024 + k];
#pragma unroll
        for (int j = 0; j < 4; j++) b[j] = emb[(size_t)(128 + 4 * l + j) * 1024 + k];
        float s = a[0] * a[0] + a[1] * a[1] + a[2] * a[2] + a[3] * a[3]
                + b[0] * b[0] + b[1] * b[1] + b[2] * b[2] + b[3] * b[3];
#pragma unroll
        for (int o = 16; o; o >>= 1) s += __shfl_xor_sync(0xFFFFFFFFu, s, o);
        if (l == 0) g_colnorm[k] = s;
        float4* et = (float4*)(g_embT + (size_t)k * 256);
        et[l]      = make_float4(a[0], a[1], a[2], a[3]);
        et[l + 32] = make_float4(b[0], b[1], b[2], b[3]);
        size_t base = (size_t)(k >> 7) * SLAB_B + (size_t)(k & 127) * 80 + (l & 7) * 8;
        st_bf16x4(g_Bimg + base + (size_t)(l >> 3) * TILE_B, a[0], a[1], a[2], a[3]);
        st_bf16x4(g_Bimg + base + (size_t)(4 + (l >> 3)) * TILE_B, b[0], b[1], b[2], b[3]);
    } else {
        int n = (blockIdx.x - 128) * 8 + w;
        const float4* p = (const float4*)(x + (size_t)n * C_DIM);
        float4 a = p[l];
        float4 b = p[l + 32];
        float s = a.x * a.x + a.y * a.y + a.z * a.z + a.w * a.w
                + b.x * b.x + b.y * b.y + b.z * b.z + b.w * b.w;
#pragma unroll
        for (int o = 16; o; o >>= 1) s += __shfl_xor_sync(0xFFFFFFFFu, s, o);
        if (l == 0) g_rownorm[n] = s;
        size_t base = (size_t)(n >> 7) * SLAB_B + (size_t)(n & 127) * 80 + (l & 7) * 8;
        st_bf16x4(g_Aimg + base + (size_t)(l >> 3) * TILE_B, a.x, a.y, a.z, a.w);
        st_bf16x4(g_Aimg + base + (size_t)(4 + (l >> 3)) * TILE_B, b.x, b.y, b.z, b.w);
    }
}

// ------------------------- K2: bf16 GEMM (round-15 config, unchanged) ----------
#define NSTAGE 4
#define ST_BO  10240
#define STAGE  20480
#define SMEM_GEMM 83968          // 2048 header + 4*20480
// header: cnt_s[128] @0 | rowmin[128][2] @512 | full[4] @1536 | empty[4] @1568

__global__ void __launch_bounds__(256, 2) k_gemm_mma() {
    extern __shared__ char smem[];
    uint32_t sb = smem_u32(smem);
    int tid = threadIdx.x, w = tid >> 5, l = tid & 31;
    int wm = w & 3, wn = w >> 2;
    int bx = blockIdx.x, by = blockIdx.y;

    int*   cnt_s  = (int*)smem;                 // [128]
    float* rowmin = (float*)(smem + 512);       // [128][2]
    if (tid < 128) cnt_s[tid] = 0;
    if (tid < NSTAGE) {
        MBAR_INIT(sb + 1536 + 8 * tid, 1);      // full
        MBAR_INIT(sb + 1568 + 8 * tid, 8);      // empty (8 warps)
    }
    __syncthreads();

    const unsigned char* Ag = g_Aimg + (size_t)by * SLAB_B;
    const unsigned char* Bg = g_Bimg + (size_t)bx * SLAB_B;
    uint32_t st_base = sb + 2048;

    if (tid == 0) {
#pragma unroll
        for (int p = 0; p < NSTAGE; p++) {
            MBAR_EXPECT(sb + 1536 + 8 * p, STAGE);
            bulk_g2s(st_base + p * STAGE,         Ag + p * TILE_B, TILE_B, sb + 1536 + 8 * p);
            bulk_g2s(st_base + p * STAGE + ST_BO, Bg + p * TILE_B, TILE_B, sb + 1536 + 8 * p);
        }
    }

    float acc[2][8][4];
#pragma unroll
    for (int f = 0; f < 2; f++)
#pragma unroll
        for (int t = 0; t < 8; t++)
#pragma unroll
            for (int j = 0; j < 4; j++) acc[f][t][j] = 0.f;

    uint32_t lrow = l & 15, lk = (l >> 4) * 16;
    uint32_t a0_off = (wm * 32 + lrow) * 80 + lk;
    uint32_t a1_off = a0_off + 16 * 80;
    uint32_t b_off  = ST_BO + (wn * 64 + lrow) * 80 + lk;

    for (int ks = 0; ks < 8; ks++) {
        int slot = ks & 3;
        mbar_wait(sb + 1536 + 8 * slot, (uint32_t)((ks >> 2) & 1));

        uint32_t base = st_base + slot * STAGE;
#pragma unroll
        for (int s = 0; s < 2; s++) {
            uint32_t A0[4], A1[4];
            ldsm4(A0, base + a0_off + s * 32);
            ldsm4(A1, base + a1_off + s * 32);
#pragma unroll
            for (int p = 0; p < 4; p++) {
                uint32_t B[4];
                ldsm4(B, base + b_off + p * 1280 + s * 32);
                mma16816(acc[0][2 * p],     A0, B[0], B[2]);
                mma16816(acc[0][2 * p + 1], A0, B[1], B[3]);
                mma16816(acc[1][2 * p],     A1, B[0], B[2]);
                mma16816(acc[1][2 * p + 1], A1, B[1], B[3]);
            }
        }
        if (l == 0) MBAR_ARRIVE(sb + 1568 + 8 * slot);

        if (w == 0 && ks < 4) {
            mbar_wait(sb + 1568 + 8 * slot, 0u);
            if (l == 0) {
                MBAR_EXPECT(sb + 1536 + 8 * slot, STAGE);
                bulk_g2s(st_base + slot * STAGE,         Ag + (ks + 4) * TILE_B, TILE_B, sb + 1536 + 8 * slot);
                bulk_g2s(st_base + slot * STAGE + ST_BO, Bg + (ks + 4) * TILE_B, TILE_B, sb + 1536 + 8 * slot);
            }
        }
    }

    // ---- Epilogue phase 1: per-(row, warp) mins -> rowmin[lr][wn] ----
    float rn[2][2];
#pragma unroll
    for (int f = 0; f < 2; f++) {
        int lr0 = wm * 32 + f * 16 + (l >> 2);
        rn[f][0] = g_rownorm[by * 128 + lr0];
        rn[f][1] = g_rownorm[by * 128 + lr0 + 8];
        float bv0 = 3.4e38f, bv1 = 3.4e38f;
#pragma unroll
        for (int t = 0; t < 8; t++) {
#pragma unroll
            for (int j = 0; j < 2; j++) {
                bv0 = fminf(bv0, rn[f][0] - 2.0f * acc[f][t][j]);
                bv1 = fminf(bv1, rn[f][1] - 2.0f * acc[f][t][j + 2]);
            }
        }
#pragma unroll
        for (int m = 1; m <= 2; m <<= 1) {
            bv0 = fminf(bv0, __shfl_xor_sync(0xFFFFFFFFu, bv0, m));
            bv1 = fminf(bv1, __shfl_xor_sync(0xFFFFFFFFu, bv1, m));
        }
        if ((l & 3) == 0) {
            int lr = wm * 32 + f * 16 + (l >> 2);
            rowmin[lr * 2 + wn]       = bv0;
            rowmin[(lr + 8) * 2 + wn] = bv1;
        }
    }
    __syncthreads();

    // ---- Epilogue phase 2: threshold = CTA-min(128 codes) + MARGIN; append ----
#pragma unroll
    for (int f = 0; f < 2; f++) {
        int lr0 = wm * 32 + f * 16 + (l >> 2);
        int r0 = by * 128 + lr0;
        float th0 = fminf(rowmin[lr0 * 2], rowmin[lr0 * 2 + 1]) + MARGIN;
        float th1 = fminf(rowmin[(lr0 + 8) * 2], rowmin[(lr0 + 8) * 2 + 1]) + MARGIN;
#pragma unroll
        for (int t = 0; t < 8; t++) {
#pragma unroll
            for (int j = 0; j < 2; j++) {
                int col = (bx * 2 + wn) * 64 + t * 8 + 2 * (l & 3) + j;
                float d0 = rn[f][0] - 2.0f * acc[f][t][j];
                float d1 = rn[f][1] - 2.0f * acc[f][t][j + 2];
                if (d0 <= th0) {
                    int pos = atomicAdd(&cnt_s[lr0], 1);
                    if (pos < RSLOTS)
                        g_cand[(size_t)r0 * 64 + bx * RSLOTS + pos] =
                            make_float2(d0, __int_as_float(col));
                }
                if (d1 <= th1) {
                    int pos = atomicAdd(&cnt_s[lr0 + 8], 1);
                    if (pos < RSLOTS)
                        g_cand[(size_t)(r0 + 8) * 64 + bx * RSLOTS + pos] =
                            make_float2(d1, __int_as_float(col));
                }
            }
        }
    }
    __syncthreads();
    if (tid < 128) {
        int c = cnt_s[tid];
        g_ccnt8[(by * 128 + tid) * 8 + bx] = c < RSLOTS ? c : RSLOTS;
    }
}

// ------------------------- K3: refine (round-15 version, unchanged) ------------
__global__ void __launch_bounds__(256) k_refineq(const float* __restrict__ x,
                                                 float* __restrict__ out_quant) {
    __shared__ float xs[2048];
    __shared__ float ws[8];
    __shared__ int   cbuf[8][32];
    int tid = threadIdx.x, w = tid >> 5, l = tid & 31;
    int row = blockIdx.x * 8 + w;

    const float2* cp = &g_cand[(size_t)row * 64];
    float2 c0 = cp[l];
    float2 c1 = cp[l + 32];
    int cntv = (l < 8) ? g_ccnt8[(size_t)row * 8 + l] : 0;
    const float4* xg = (const float4*)(x + (size_t)row * 256);
    float4 xa = xg[l];
    float4 xb = xg[l + 32];
    float rnv = g_rownorm[row];

    float4* xrow4 = (float4*)(xs + w * 256);
    xrow4[l]      = xa;
    xrow4[l + 32] = xb;

    int cnt_r0 = __shfl_sync(0xFFFFFFFFu, cntv, l >> 3);
    int cnt_r1 = __shfl_sync(0xFFFFFFFFu, cntv, 4 + (l >> 3));
    int s_in = l & 7;
    bool val0 = s_in < cnt_r0;
    bool val1 = s_in < cnt_r1;

    float m0 = val0 ? c0.x : 3.4e38f;
    float m1 = val1 ? c1.x : 3.4e38f;
    float cm = fminf(m0, m1);
#pragma unroll
    for (int o = 16; o; o >>= 1) cm = fminf(cm, __shfl_xor_sync(0xFFFFFFFFu, cm, o));
    float thresh = cm + MARGIN;

    int v0 = (val0 && c0.x <= thresh) ? 1 : 0;
    int v1 = (val1 && c1.x <= thresh) ? 1 : 0;
    int nv = v0 + v1;
    int pre = nv;
#pragma unroll
    for (int o = 1; o < 32; o <<= 1) {
        int t = __shfl_up_sync(0xFFFFFFFFu, pre, o);
        if (l >= o) pre += t;
    }
    int excl = pre - nv;
    int total = __shfl_sync(0xFFFFFFFFu, pre, 31);
    if (total > 32) total = 32;

    int* buf = cbuf[w];
    int p = excl;
    if (v0 && p < 32) buf[p++] = __float_as_int(c0.y);
    if (v1 && p < 32) buf[p++] = __float_as_int(c1.y);
    __syncwarp();

    int k;
    if (total == 1) {
        k = buf[0];
    } else {
        int mycand = (l < total) ? buf[l] : -1;
        float dval = 3.4e38f;
        int   didx = 0x7FFFFFFF;
        if (mycand >= 0) {
            const float4* e4 = (const float4*)(g_embT + (size_t)mycand * 256);
            const float4* x4 = (const float4*)(xs + w * 256);
            float acc = 0.f;
#pragma unroll 4
            for (int i = 0; i < 64; i++) {
                float4 e = e4[i];
                float4 xv = x4[i];
                acc = fmaf(xv.x, e.x, acc);
                acc = fmaf(xv.y, e.y, acc);
                acc = fmaf(xv.z, e.z, acc);
                acc = fmaf(xv.w, e.w, acc);
            }
            dval = (rnv - 2.0f * acc) + g_colnorm[mycand];
            didx = mycand;
        }
#pragma unroll
        for (int o = 16; o; o >>= 1) {
            float ov = __shfl_xor_sync(0xFFFFFFFFu, dval, o);
            int   oi = __shfl_xor_sync(0xFFFFFFFFu, didx, o);
            if (ov < dval || (ov == dval && oi < didx)) { dval = ov; didx = oi; }
        }
        k = didx;
    }
    if (l == 0) {
        g_idx[row] = k;
        atomicAdd(&g_counts[k], 1);
    }

    const float4* e4 = (const float4*)(g_embT + (size_t)k * 256);
    float4 ea = e4[l];
    float4 eb = e4[l + 32];
    float4* q4 = (float4*)(out_quant + (size_t)row * 256);
    float lsum = 0.f;
    {
        float dx = ea.x - xa.x, dy = ea.y - xa.y, dz = ea.z - xa.z, dw2 = ea.w - xa.w;
        float4 o;
        o.x = xa.x + dx; o.y = xa.y + dy; o.z = xa.z + dz; o.w = xa.w + dw2;
        q4[l] = o;
        lsum += dx * dx + dy * dy + dz * dz + dw2 * dw2;
    }
    {
        float dx = eb.x - xb.x, dy = eb.y - xb.y, dz = eb.z - xb.z, dw2 = eb.w - xb.w;
        float4 o;
        o.x = xb.x + dx; o.y = xb.y + dy; o.z = xb.z + dz; o.w = xb.w + dw2;
        q4[l + 32] = o;
        lsum += dx * dx + dy * dy + dz * dz + dw2 * dw2;
    }
#pragma unroll
    for (int o = 16; o; o >>= 1) lsum += __shfl_xor_sync(0xFFFFFFFFu, lsum, o);
    if (l == 0) ws[w] = lsum;
    __syncthreads();
    if (tid < 8) {
        float v = ws[tid];
#pragma unroll
        for (int o = 4; o; o >>= 1) v += __shfl_xor_sync(0x000000FFu, v, o);
        if (tid == 0) atomicAdd(&g_loss, (double)v);
    }
}

// ------------------------- K4: scan (round-15 version) -------------------------
__global__ void k_scan(const float* __restrict__ ema_cs, float* __restrict__ out) {
    __shared__ int   si[1024];
    __shared__ float red[1024];
    int t = threadIdx.x;
    int cnt = g_counts[t];

    si[t] = cnt; __syncthreads();
    for (int o = 1; o < 1024; o <<= 1) {
        int v = (t >= o) ? si[t - o] : 0;
        __syncthreads();
        si[t] += v;
        __syncthreads();
    }
    g_base[t] = si[t] - cnt;

    float cs = ema_cs[t] * 0.99f + (float)cnt * 0.01f;
    out[OFF_CS + t] = cs;

    red[t] = cs; __syncthreads();
    for (int s = 512; s > 0; s >>= 1) {
        if (t < s) red[t] += red[t + s];
        __syncthreads();
    }
    float n = red[0];
    __syncthreads();

    float p = (float)cnt / 32768.0f;
    red[t] = p * logf(p + 1e-10f); __syncthreads();
    for (int s = 512; s > 0; s >>= 1) {
        if (t < s) red[t] += red[t + s];
        __syncthreads();
    }
    if (t == 0) {
        out[OFF_PERP] = expf(-red[0]);
        out[OFF_LOSS] = 0.25f * (float)(g_loss / 8388608.0);
    }
    g_smoothed[t] = (cs + 1e-5f) / (n + 0.01024f) * n;
}

// ------------------------- K5: bucket rows by code (round-15 version) ----------
__global__ void k_fill() {
    int row = blockIdx.x * 256 + threadIdx.x;
    int k = g_idx[row];
    int pos = atomicAdd(&g_cursor[k], 1);
    g_rows[g_base[k] + pos] = row;
}

// ------------------------- K6: dw + new embeddings (fused) ---------------------
__global__ void k_dw(const float* __restrict__ x,
                     const float* __restrict__ ema_dw,
                     float* __restrict__ out) {
    int k = blockIdx.x, c = threadIdx.x;
    int cnt = g_counts[k], base = g_base[k];
    float a0 = 0.f, a1 = 0.f, a2 = 0.f, a3 = 0.f;
    int i = 0;
    for (; i + 4 <= cnt; i += 4) {
        int r0 = g_rows[base + i],     r1 = g_rows[base + i + 1];
        int r2 = g_rows[base + i + 2], r3 = g_rows[base + i + 3];
        a0 += x[(size_t)r0 * 256 + c];
        a1 += x[(size_t)r1 * 256 + c];
        a2 += x[(size_t)r2 * 256 + c];
        a3 += x[(size_t)r3 * 256 + c];
    }
    for (; i < cnt; i++) a0 += x[(size_t)g_rows[base + i] * 256 + c];
    float sum = (a0 + a1) + (a2 + a3);
    float dwv = ema_dw[c * 1024 + k] * 0.99f + 0.01f * sum;
    out[OFF_DW  + c * 1024 + k] = dwv;
    out[OFF_EMB + c * 1024 + k] = dwv / g_smoothed[k];
}

// ------------------------- launch -------------------------
extern "C" void kernel_launch(void* const* d_in, const int* in_sizes, int n_in,
                              void* d_out, int out_size) {
    const float* x      = (const float*)d_in[0];
    const float* emb    = (const float*)d_in[1];
    const float* ema_cs = (const float*)d_in[2];
    const float* ema_dw = (const float*)d_in[3];
    float* out = (float*)d_out;

    cudaFuncSetAttribute(k_gemm_mma, cudaFuncAttributeMaxDynamicSharedMemorySize,
                         SMEM_GEMM);

    k_init      <<<1, 1024>>>();                                  // 1
    k_prep      <<<4224, 256>>>(emb, x);                          // 2 (merged)
    k_gemm_mma  <<<dim3(8, 256), 256, SMEM_GEMM>>>();             // 3
    k_refineq   <<<4096, 256>>>(x, out + OFF_QUANT);              // 4 (profiled)
    k_scan      <<<1, 1024>>>(ema_cs, out);                       // 5
    k_fill      <<<128, 256>>>();                                 // 6
    k_dw        <<<1024, 256>>>(x, ema_dw, out);                  // 7
}